// round 6
// baseline (speedup 1.0000x reference)
#include <cuda_runtime.h>
#include <cuda_bf16.h>
#include <cstdint>

#define NM     512
#define BATCH  32
#define DIMK   64
#define BIGF   1e30f
#define SENTU  0x7fc00000u

// Diagonal layout: Dd[b][t][i], t=i+j, row stride 512; 1024 rows/batch + pad.
#define TROWS   1024
#define BSTRIDE (TROWS * NM)
__device__ float g_Dd[(size_t)BATCH * BSTRIDE + 16384];

// Cross-CTA boundary ring (row 255 -> 256), data-is-flag. 640 floats/batch:
// cols live at [32, 544), aprons BIG on both sides (overread-safe).
#define GROW 640
__device__ float g_bnd[BATCH * GROW];

// smem boundary rows: 576 floats; col c at index 32+c.
#define ROWLEN 576

__device__ __forceinline__ float ex2f(float x) {
    float r; asm("ex2.approx.f32 %0, %1;" : "=f"(r) : "f"(x)); return r;
}
__device__ __forceinline__ float lg2f(float x) {
    float r; asm("lg2.approx.f32 %0, %1;" : "=f"(r) : "f"(x)); return r;
}
// smem spin (raw backward branch, no BSSY): wait until *p != sentinel.
__device__ __forceinline__ float spin_lds(const float* p) {
    unsigned a = (unsigned)__cvta_generic_to_shared(p);
    unsigned v;
    asm volatile(
        "{\n\t.reg .pred sp;\n"
        "SPINS%=:\n\t"
        "ld.volatile.shared.b32 %0, [%1];\n\t"
        "setp.eq.u32 sp, %0, 0x7fc00000;\n\t"
        "@sp bra SPINS%=;\n\t}"
        : "=r"(v) : "r"(a) : "memory");
    return __uint_as_float(v);
}
// global spin (L2-coherent volatile)
__device__ __forceinline__ float spin_ldg(const float* p) {
    unsigned v;
    asm volatile(
        "{\n\t.reg .pred sp;\n"
        "SPING%=:\n\t"
        "ld.volatile.global.b32 %0, [%1];\n\t"
        "setp.eq.u32 sp, %0, 0x7fc00000;\n\t"
        "@sp bra SPING%=;\n\t}"
        : "=r"(v) : "l"(p) : "memory");
    return __uint_as_float(v);
}
__device__ __forceinline__ float4 vldg4(const float* p) {
    float4 r;
    asm volatile("ld.volatile.global.v4.f32 {%0,%1,%2,%3}, [%4];"
                 : "=f"(r.x), "=f"(r.y), "=f"(r.z), "=f"(r.w) : "l"(p) : "memory");
    return r;
}
__device__ __forceinline__ void stg_vol(float* p, float v) {
    asm volatile("st.volatile.global.b32 [%0], %1;" :: "l"(p), "f"(v) : "memory");
}

// ---------------------------------------------------------------------------
// Kernel 0: init cross-CTA boundary ring to sentinel/apron pattern.
// ---------------------------------------------------------------------------
__global__ void binit_kernel()
{
    int t = blockIdx.x * 512 + threadIdx.x;
    if (t < BATCH * GROW) {
        int col = t % GROW;
        bool sent = (col >= 32) && (col < 32 + NM);
        g_bnd[t] = sent ? __uint_as_float(SENTU) : BIGF;
    }
}

// ---------------------------------------------------------------------------
// Kernel 1: Dd[b][i+j][i] = sqdist * log2(e). 64x64 tiles, 4x4 microtiles,
// diagonal-coalesced writeout.
// ---------------------------------------------------------------------------
__global__ void __launch_bounds__(256) pairdist_kernel(
    const float* __restrict__ X, const float* __restrict__ Y)
{
    __shared__ __align__(16) float Xs[64 * 68];
    __shared__ __align__(16) float Ys[64 * 68];
    __shared__ __align__(16) float x2s[64];
    __shared__ __align__(16) float y2s[64];
    __shared__ __align__(16) float stage[64 * 64];

    const int b  = blockIdx.z;
    const int i0 = blockIdx.x * 64;
    const int j0 = blockIdx.y * 64;
    const int tid = threadIdx.x;

    const float* Xb = X + ((size_t)b * NM + i0) * DIMK;
    const float* Yb = Y + ((size_t)b * NM + j0) * DIMK;

    for (int t = tid; t < 64 * 64; t += 256) {
        int r = t >> 6, k = t & 63;
        Xs[k * 68 + r] = Xb[r * DIMK + k];
        Ys[k * 68 + r] = Yb[r * DIMK + k];
    }
    __syncthreads();

    if (tid < 128) {
        int r = tid & 63;
        const float* S = (tid < 64) ? Xs : Ys;
        float acc = 0.f;
        #pragma unroll 8
        for (int k = 0; k < 64; ++k) { float v = S[k * 68 + r]; acc += v * v; }
        if (tid < 64) x2s[r] = acc; else y2s[r] = acc;
    }
    __syncthreads();

    const int tx = tid & 15, ty = tid >> 4;
    float acc[4][4];
    #pragma unroll
    for (int a = 0; a < 4; ++a)
        #pragma unroll
        for (int c = 0; c < 4; ++c) acc[a][c] = 0.f;

    #pragma unroll 8
    for (int k = 0; k < 64; ++k) {
        float4 xv = *(const float4*)&Xs[k * 68 + 4 * tx];
        float4 yv = *(const float4*)&Ys[k * 68 + 4 * ty];
        float xr[4] = {xv.x, xv.y, xv.z, xv.w};
        float yr[4] = {yv.x, yv.y, yv.z, yv.w};
        #pragma unroll
        for (int jj = 0; jj < 4; ++jj)
            #pragma unroll
            for (int ii = 0; ii < 4; ++ii)
                acc[jj][ii] += yr[jj] * xr[ii];
    }

    const float L2E = 1.4426950408889634f;
    float4 x2v = *(const float4*)&x2s[4 * tx];
    float xr2[4] = {x2v.x, x2v.y, x2v.z, x2v.w};
    #pragma unroll
    for (int jj = 0; jj < 4; ++jj) {
        float y2 = y2s[4 * ty + jj];
        #pragma unroll
        for (int ii = 0; ii < 4; ++ii)
            stage[(4 * ty + jj) * 64 + 4 * tx + ii] =
                (xr2[ii] + y2 - 2.f * acc[jj][ii]) * L2E;
    }
    __syncthreads();

    const int w    = tid >> 5;
    const int lane = tid & 31;
    const int tbase = i0 + j0;
    float* gout = g_Dd + (size_t)b * BSTRIDE;
    for (int td = w; td < 127; td += 8) {
        int lo = td > 63 ? td - 63 : 0;
        int hi = td < 63 ? td : 63;
        for (int il = lo + lane; il <= hi; il += 32) {
            float v = stage[(td - il) * 64 + il];
            gout[(size_t)(tbase + td) * NM + i0 + il] = v;
        }
    }
}

// ---------------------------------------------------------------------------
// Kernel 2: soft-DTW wavefront. 2 CTAs per batch (rows 0-255 / 256-511),
// 8 warps each. Lane k of warp w owns row R0+32w+k; step s computes j=s-lane.
// In-CTA boundaries via smem data-is-flag; cross-CTA via global data-is-flag.
// softmin with 2xEX2+1xLG2 (min term's exp == 1).
// ---------------------------------------------------------------------------
__global__ void __launch_bounds__(256, 1) sdtw_kernel(float* __restrict__ out)
{
    __shared__ __align__(16) float buf[9 * ROWLEN];

    const int bx   = blockIdx.x;
    const int b    = bx >> 1;
    const int half = bx & 1;
    const int tid  = threadIdx.x;
    const int w    = tid >> 5;
    const int lane = tid & 31;
    const bool is31 = (lane == 31);
    const int R0   = 256 * half + 32 * w;

    for (int t = tid; t < 9 * ROWLEN; t += 256) {
        int row = t / ROWLEN, col = t % ROWLEN;
        bool sent = (row >= 1) && (col >= 32) && (col < 32 + NM);
        buf[t] = sent ? __uint_as_float(SENTU) : BIGF;
    }
    __syncthreads();

    // D prefetch ring: consume Dd row t=R0+s at step s; prefetch 8 ahead.
    const float* dp = g_Dd + (size_t)b * BSTRIDE + (size_t)(R0 + 8) * NM + R0 + lane;
    float dring[8];
    #pragma unroll
    for (int p = 0; p < 8; ++p) dring[p] = dp[(p - 8) * NM];

    const bool gpoll  = (half == 1) && (w == 0);   // consume from global ring
    const bool gstore = (half == 0) && (w == 7);   // produce into global ring
    const float* brow  = &buf[w * ROWLEN];
    float*       prow  = &buf[(w + 1) * ROWLEN + 1];
    const float* gbrow = g_bnd + b * GROW;
    float*       gprow = g_bnd + b * GROW + 1;

    // Initial chunk: cols 0..7
    float bnd[8];
    {
        float4 c0, c1;
        if (gpoll) {
            (void)spin_ldg(gbrow + 39);
            c0 = vldg4(gbrow + 32);
            c1 = vldg4(gbrow + 36);
        } else {
            (void)spin_lds(brow + 39);
            c0 = *(const float4*)(brow + 32);
            c1 = *(const float4*)(brow + 36);
        }
        bnd[0]=c0.x; bnd[1]=c0.y; bnd[2]=c0.z; bnd[3]=c0.w;
        bnd[4]=c1.x; bnd[5]=c1.y; bnd[6]=c1.z; bnd[7]=c1.w;
    }

    float res  = 0.f;
    float left = BIGF;
    float up1  = (lane == 0) ? bnd[0] : BIGF;
    float up2  = (half == 0 && tid == 0) ? 0.0f : BIGF;
    float lo   = fminf(up1, up2);
    float hi   = fmaxf(up1, up2);

    for (int B = 0; B < 544; B += 8) {
        #pragma unroll
        for (int u = 0; u < 8; ++u) {
            float d = dring[u];
            dring[u] = dp[u * NM];                  // prefetch row +8

            // softmin (log2 domain): one exp term is exactly 1.
            float m  = fminf(lo, left);
            float x  = fmaxf(lo, left);
            float e1 = ex2f(m - x);
            float e2 = ex2f(m - hi);
            float lg = lg2f((e1 + e2) + 1.0f);
            float v  = (d + m) - lg;

            if (u == 6) { if (B == 536) res = v; }  // s==542: R[511][511]

            if (is31) {                              // boundary stream
                if (gstore) stg_vol(gprow + B + u, v);
                else        *(volatile float*)(prow + B + u) = v;
            }

            float sh = __shfl_up_sync(0xffffffffu, v, 1);

            if (u == 7) {                            // chunk for next block
                float4 c0, c1;
                if (gpoll) {
                    (void)spin_ldg(gbrow + 39 + (B + 8));
                    c0 = vldg4(gbrow + 32 + (B + 8));
                    c1 = vldg4(gbrow + 36 + (B + 8));
                } else {
                    (void)spin_lds(brow + 39 + (B + 8));
                    c0 = *(const float4*)(brow + 32 + (B + 8));
                    c1 = *(const float4*)(brow + 36 + (B + 8));
                }
                bnd[0]=c0.x; bnd[1]=c0.y; bnd[2]=c0.z; bnd[3]=c0.w;
                bnd[4]=c1.x; bnd[5]=c1.y; bnd[6]=c1.z; bnd[7]=c1.w;
            }

            up2  = up1;
            up1  = (lane == 0) ? bnd[(u + 1) & 7] : sh;
            left = v;
            lo   = fminf(up1, up2);
            hi   = fmaxf(up1, up2);
        }
        dp += 8 * NM;
    }

    if (half == 1 && tid == 255)
        out[b] = res * 0.69314718055994531f;         // log2 -> natural domain
}

extern "C" void kernel_launch(void* const* d_in, const int* in_sizes, int n_in,
                              void* d_out, int out_size)
{
    (void)in_sizes; (void)n_in; (void)out_size;
    const float* X = (const float*)d_in[0];
    const float* Y = (const float*)d_in[1];
    float* out = (float*)d_out;

    binit_kernel<<<(BATCH * GROW + 511) / 512, 512>>>();
    dim3 g1(NM / 64, NM / 64, BATCH);
    pairdist_kernel<<<g1, 256>>>(X, Y);
    sdtw_kernel<<<2 * BATCH, 256>>>(out);
}

// round 7
// speedup vs baseline: 1.3795x; 1.3795x over previous
#include <cuda_runtime.h>
#include <cuda_bf16.h>
#include <cstdint>

#define NM     512
#define BATCH  32
#define DIMK   64
#define BIGF   1e30f
#define SENTU  0x7fc00000u

// Packed D (pre-scaled by log2 e): g_Dp[b][w][s][64], w=row-group (64 rows),
// s=step, slot il=2k+r -> Dsc[i=64w+il][j=s-k]. Zero where j out of range
// (device globals are zero-initialized). +pad for prefetch overrun.
#define SROWS 544
__device__ __align__(16) float g_Dp[(size_t)BATCH * 8 * SROWS * 64 + 2048];

// smem boundary rows: 576 floats; col c at index 32+c.
#define ROWLEN 576

__device__ __forceinline__ float ex2f(float x) {
    float r; asm("ex2.approx.f32 %0, %1;" : "=f"(r) : "f"(x)); return r;
}
__device__ __forceinline__ float lg2f(float x) {
    float r; asm("lg2.approx.f32 %0, %1;" : "=f"(r) : "f"(x)); return r;
}
// smem spin (raw backward branch, no BSSY): wait until *p != sentinel.
__device__ __forceinline__ float spin_lds(const float* p) {
    unsigned a = (unsigned)__cvta_generic_to_shared(p);
    unsigned v;
    asm volatile(
        "{\n\t.reg .pred sp;\n"
        "SPINS%=:\n\t"
        "ld.volatile.shared.b32 %0, [%1];\n\t"
        "setp.eq.u32 sp, %0, 0x7fc00000;\n\t"
        "@sp bra SPINS%=;\n\t}"
        : "=r"(v) : "r"(a) : "memory");
    return __uint_as_float(v);
}

// ---------------------------------------------------------------------------
// Kernel 1: pairwise sqdist * log2(e), packed directly into g_Dp layout.
// 64x64 tiles, 256 threads, 4x4 microtiles. stage aliases Xs (reused).
// ---------------------------------------------------------------------------
__global__ void __launch_bounds__(256) pairdist_kernel(
    const float* __restrict__ X, const float* __restrict__ Y)
{
    __shared__ __align__(16) float Xs[64 * 68];   // later reused as stage[jl][il], stride 65
    __shared__ __align__(16) float Ys[64 * 68];
    __shared__ __align__(16) float x2s[64];
    __shared__ __align__(16) float y2s[64];

    const int b  = blockIdx.z;
    const int i0 = blockIdx.x * 64;
    const int j0 = blockIdx.y * 64;
    const int tid = threadIdx.x;

    const float* Xb = X + ((size_t)b * NM + i0) * DIMK;
    const float* Yb = Y + ((size_t)b * NM + j0) * DIMK;

    for (int t = tid; t < 64 * 64; t += 256) {
        int r = t >> 6, k = t & 63;
        Xs[k * 68 + r] = Xb[r * DIMK + k];
        Ys[k * 68 + r] = Yb[r * DIMK + k];
    }
    __syncthreads();

    if (tid < 128) {
        int r = tid & 63;
        const float* S = (tid < 64) ? Xs : Ys;
        float acc = 0.f;
        #pragma unroll 8
        for (int k = 0; k < 64; ++k) { float v = S[k * 68 + r]; acc += v * v; }
        if (tid < 64) x2s[r] = acc; else y2s[r] = acc;
    }
    __syncthreads();

    const int tx = tid & 15, ty = tid >> 4;
    float acc[4][4];
    #pragma unroll
    for (int a = 0; a < 4; ++a)
        #pragma unroll
        for (int c = 0; c < 4; ++c) acc[a][c] = 0.f;

    #pragma unroll 8
    for (int k = 0; k < 64; ++k) {
        float4 xv = *(const float4*)&Xs[k * 68 + 4 * tx];
        float4 yv = *(const float4*)&Ys[k * 68 + 4 * ty];
        float xr[4] = {xv.x, xv.y, xv.z, xv.w};
        float yr[4] = {yv.x, yv.y, yv.z, yv.w};
        #pragma unroll
        for (int jj = 0; jj < 4; ++jj)
            #pragma unroll
            for (int ii = 0; ii < 4; ++ii)
                acc[jj][ii] += yr[jj] * xr[ii];
    }

    const float L2E = 1.4426950408889634f;
    float4 x2v = *(const float4*)&x2s[4 * tx];
    float xr2[4] = {x2v.x, x2v.y, x2v.z, x2v.w};
    float outv[4][4];
    #pragma unroll
    for (int jj = 0; jj < 4; ++jj) {
        float y2 = y2s[4 * ty + jj];
        #pragma unroll
        for (int ii = 0; ii < 4; ++ii)
            outv[jj][ii] = (xr2[ii] + y2 - 2.f * acc[jj][ii]) * L2E;
    }
    __syncthreads();                      // all Xs reads done -> reuse as stage

    float* stage = Xs;                    // stage[jl*65 + il]
    #pragma unroll
    for (int jj = 0; jj < 4; ++jj)
        #pragma unroll
        for (int ii = 0; ii < 4; ++ii)
            stage[(4 * ty + jj) * 65 + 4 * tx + ii] = outv[jj][ii];
    __syncthreads();

    // Packed writeout: for s-row sd (global s=j0+sd), lane handles k=lo2+lane,
    // writes float2 {stage[jl][2k], stage[jl][2k+1]}, jl = sd-k.
    const int wk   = tid >> 5;
    const int lane = tid & 31;
    float* gout = g_Dp + ((size_t)(b * 8 + blockIdx.x) * SROWS + j0) * 64;
    for (int sd = wk; sd < 95; sd += 8) {
        int lo2 = sd > 63 ? sd - 63 : 0;
        int hi2 = sd < 31 ? sd : 31;
        int k = lo2 + lane;
        if (k <= hi2) {
            int jl = sd - k;
            float2 p;
            p.x = stage[jl * 65 + 2 * k];
            p.y = stage[jl * 65 + 2 * k + 1];
            *(float2*)(gout + (size_t)sd * 64 + 2 * k) = p;
        }
    }
}

// ---------------------------------------------------------------------------
// Kernel 2: soft-DTW wavefront. 1 CTA/batch, 8 warps; lane k of warp w owns
// rows i0=64w+2k, i1=i0+1; step s computes column j=s-k for both rows.
// Cell1 is intra-lane (no shfl). Boundary rows (i=64w+63) stream via smem
// data-is-flag. min/max pairs hoisted off the dependency chain.
// ---------------------------------------------------------------------------
__global__ void __launch_bounds__(256, 1) sdtw_kernel(float* __restrict__ out)
{
    __shared__ __align__(16) float buf[9 * ROWLEN];

    const int b    = blockIdx.x;
    const int tid  = threadIdx.x;
    const int w    = tid >> 5;
    const int lane = tid & 31;
    const bool is0  = (lane == 0);
    const bool is31 = (lane == 31);

    // row 0: virtual BIG row; rows 1..8: sentinel in col region, BIG aprons.
    for (int t = tid; t < 9 * ROWLEN; t += 256) {
        int row = t / ROWLEN, col = t % ROWLEN;
        bool sent = (row >= 1) && (col >= 32) && (col < 32 + NM);
        buf[t] = sent ? __uint_as_float(SENTU) : BIGF;
    }
    __syncthreads();

    // D prefetch ring (float2 per lane per step; row stride 32 float2).
    const float2* dbase = (const float2*)(g_Dp + (size_t)(b * 8 + w) * SROWS * 64) + lane;
    float2 dring[8];
    #pragma unroll
    for (int p = 0; p < 8; ++p) dring[p] = dbase[p * 32];
    const float2* dp = dbase + 8 * 32;

    const float* brow = &buf[w * ROWLEN];            // consumer: col c at 32+c
    float*       prow = &buf[(w + 1) * ROWLEN + 1];  // producer: col j at index 1+(j+31)

    float bnd[8];
    {
        (void)spin_lds(brow + 39);
        float4 c0 = *(const float4*)(brow + 32);
        float4 c1 = *(const float4*)(brow + 36);
        bnd[0]=c0.x; bnd[1]=c0.y; bnd[2]=c0.z; bnd[3]=c0.w;
        bnd[4]=c1.x; bnd[5]=c1.y; bnd[6]=c1.z; bnd[7]=c1.w;
    }

    float left0 = BIGF, left1 = BIGF;
    float diag0 = (tid == 0) ? 0.0f : BIGF;          // origin diag R[-1][-1]=0
    float up0   = is0 ? bnd[0] : BIGF;
    float lo0 = fminf(diag0, up0), hi0 = fmaxf(diag0, up0);
    float lo1 = fminf(left0, left1), hi1 = fmaxf(left0, left1);

    float res = 0.f;

    for (int B = 0; B < 544; B += 8) {
        #pragma unroll
        for (int u = 0; u < 8; ++u) {
            float2 d2 = dring[u];
            dring[u] = dp[u * 32];                   // prefetch step B+8+u

            // cell0: softmin(diag0, up0, left0); lo0/hi0 precomputed
            float m0 = fminf(lo0, left0);
            float x0 = fmaxf(lo0, left0);
            float ea = ex2f(m0 - x0);
            float eb = ex2f(m0 - hi0);
            float v0 = (d2.x + m0) - lg2f((ea + eb) + 1.0f);

            // cell1: softmin(left0, v0, left1); lo1/hi1 = min/max(left0,left1)
            float m1 = fminf(lo1, v0);
            float x1 = fmaxf(lo1, v0);
            float ec = ex2f(m1 - x1);
            float ed = ex2f(m1 - hi1);
            float v1 = (d2.y + m1) - lg2f((ec + ed) + 1.0f);

            if (u == 6) { if (B == 536) res = v1; }  // s=542: R[511][511]

            if (is31) *(volatile float*)(prow + B + u) = v1;  // bottom row stream

            float sh = __shfl_up_sync(0xffffffffu, v1, 1);

            if (u == 7) {                            // next boundary chunk
                (void)spin_lds(brow + 39 + (B + 8));
                float4 c0 = *(const float4*)(brow + 32 + (B + 8));
                float4 c1 = *(const float4*)(brow + 36 + (B + 8));
                bnd[0]=c0.x; bnd[1]=c0.y; bnd[2]=c0.z; bnd[3]=c0.w;
                bnd[4]=c1.x; bnd[5]=c1.y; bnd[6]=c1.z; bnd[7]=c1.w;
            }

            // next-step state (min/max pairs off the chain)
            diag0 = up0;
            up0   = is0 ? bnd[(u + 1) & 7] : sh;
            lo0 = fminf(diag0, up0); hi0 = fmaxf(diag0, up0);
            lo1 = fminf(v0, v1);     hi1 = fmaxf(v0, v1);
            left0 = v0; left1 = v1;
        }
        dp += 8 * 32;
    }

    if (tid == 255)
        out[b] = res * 0.69314718055994531f;         // log2 -> natural domain
}

extern "C" void kernel_launch(void* const* d_in, const int* in_sizes, int n_in,
                              void* d_out, int out_size)
{
    (void)in_sizes; (void)n_in; (void)out_size;
    const float* X = (const float*)d_in[0];
    const float* Y = (const float*)d_in[1];
    float* out = (float*)d_out;

    dim3 g1(NM / 64, NM / 64, BATCH);
    pairdist_kernel<<<g1, 256>>>(X, Y);
    sdtw_kernel<<<BATCH, 256>>>(out);
}